// round 5
// baseline (speedup 1.0000x reference)
#include <cuda_runtime.h>
#include <cuda_bf16.h>
#include <cstdint>
#include <math.h>

// queries [16,1024,256] f32 -> M=16384, embedding [8192,256] f32 -> N=8192
// Output (f32): [M indices][M*256 quantized_st][1 vq_loss]

#define M_TOTAL 16384
#define N_TOTAL 8192
#define KDIM    256

#define BM 128
#define BN 128
#define BK 16
#define TM 8
#define TN 8
#define NBLK (N_TOTAL / BN)   // 64 column blocks

// Scratch (device symbols only referenced from device code — R2's bug was
// passing these as host-side kernel args)
__device__ float g_esq[N_TOTAL];
__device__ float g_qsq[M_TOTAL];
__device__ ulonglong2 g_btop[NBLK * M_TOTAL];
__device__ int   g_final[M_TOTAL];
__device__ float g_partial[M_TOTAL];

__device__ __forceinline__ unsigned float_ordered(float f) {
    unsigned u = __float_as_uint(f);
    return (u & 0x80000000u) ? ~u : (u | 0x80000000u);
}
__device__ __forceinline__ void ins2(unsigned long long k,
                                     unsigned long long& m1,
                                     unsigned long long& m2) {
    if (k < m1) { m2 = m1; m1 = k; }
    else if (k < m2) { m2 = k; }
}
__device__ __forceinline__ void ins4(unsigned long long k, unsigned long long* m) {
    if (k < m[3]) {
        if (k < m[1]) {
            if (k < m[0]) { m[3]=m[2]; m[2]=m[1]; m[1]=m[0]; m[0]=k; }
            else          { m[3]=m[2]; m[2]=m[1]; m[1]=k; }
        } else {
            if (k < m[2]) { m[3]=m[2]; m[2]=k; }
            else          { m[3]=k; }
        }
    }
}

// ---------------------------------------------------------------------------
// XLA-GPU-row-reduce-emulating squared norms: warp per row, lane strides by
// 32 with sequential accumulation, then binary-tree shuffle reduce (the
// xor butterfly has the same association as XLA's shfl_down tree).
__global__ void qsq_kernel(const float* __restrict__ Q) {
    int row = blockIdx.x * 8 + (threadIdx.x >> 5);
    int lane = threadIdx.x & 31;
    const float* x = Q + (size_t)row * KDIM;
    float s = 0.f;
    #pragma unroll
    for (int c = lane; c < KDIM; c += 32) { float v = x[c]; s = fmaf(v, v, s) ; }
    // NOTE: XLA computes x*x then adds (mul rounds, add rounds) — NOT fused.
    // Redo without fma to match: (kept explicit below)
    s = 0.f;
    #pragma unroll
    for (int c = lane; c < KDIM; c += 32) { float v = x[c]; float p = v * v; s = s + p; }
    #pragma unroll
    for (int off = 16; off; off >>= 1) s += __shfl_xor_sync(0xffffffffu, s, off);
    if (lane == 0) g_qsq[row] = s;
}

__global__ void esq_kernel(const float* __restrict__ E) {
    int row = blockIdx.x * 8 + (threadIdx.x >> 5);
    int lane = threadIdx.x & 31;
    const float* x = E + (size_t)row * KDIM;
    float s = 0.f;
    #pragma unroll
    for (int c = lane; c < KDIM; c += 32) { float v = x[c]; float p = v * v; s = s + p; }
    #pragma unroll
    for (int off = 16; off; off >>= 1) s += __shfl_xor_sync(0xffffffffu, s, off);
    if (lane == 0) g_esq[row] = s;
}

// ---------------------------------------------------------------------------
// Fast path: score GEMM + per-(query, colblock) top-2 by ACCURATE ordering
// (dist = esq - 2*dot; candidate selection only — final decision is the
// emulated-quantized compare in refine_kernel).
__global__ __launch_bounds__(256, 2)
void score_top2_kernel(const float* __restrict__ Q, const float* __restrict__ E) {
    __shared__ float As[BK][BM];
    __shared__ float Bs[BK][BN];

    const int tid = threadIdx.x;
    const int tx = tid & 15;
    const int ty = tid >> 4;
    const int rowBase = blockIdx.x * BM;
    const int colBase = blockIdx.y * BN;

    float acc[TM][TN];
    #pragma unroll
    for (int i = 0; i < TM; i++)
        #pragma unroll
        for (int j = 0; j < TN; j++) acc[i][j] = 0.f;

    for (int kt = 0; kt < KDIM; kt += BK) {
        #pragma unroll
        for (int l = 0; l < 2; l++) {
            int li = tid + l * 256;
            int r  = li >> 2;
            int c4 = li & 3;
            float4 va = *(const float4*)(&Q[(size_t)(rowBase + r) * KDIM + kt + c4 * 4]);
            As[c4 * 4 + 0][r] = va.x; As[c4 * 4 + 1][r] = va.y;
            As[c4 * 4 + 2][r] = va.z; As[c4 * 4 + 3][r] = va.w;
            float4 vb = *(const float4*)(&E[(size_t)(colBase + r) * KDIM + kt + c4 * 4]);
            Bs[c4 * 4 + 0][r] = vb.x; Bs[c4 * 4 + 1][r] = vb.y;
            Bs[c4 * 4 + 2][r] = vb.z; Bs[c4 * 4 + 3][r] = vb.w;
        }
        __syncthreads();

        #pragma unroll
        for (int kk = 0; kk < BK; kk++) {
            float ra[TM], rb[TN];
            #pragma unroll
            for (int i = 0; i < TM; i++) ra[i] = As[kk][ty * TM + i];
            #pragma unroll
            for (int j = 0; j < TN; j++) rb[j] = Bs[kk][tx * TN + j];
            #pragma unroll
            for (int i = 0; i < TM; i++)
                #pragma unroll
                for (int j = 0; j < TN; j++)
                    acc[i][j] += ra[i] * rb[j];
        }
        __syncthreads();
    }

    #pragma unroll
    for (int i = 0; i < TM; i++) {
        int grow = rowBase + ty * TM + i;
        unsigned long long m1 = ~0ULL, m2 = ~0ULL;
        #pragma unroll
        for (int j = 0; j < TN; j++) {
            int gcol = colBase + tx * TN + j;
            float dist = g_esq[gcol] - 2.0f * acc[i][j];
            unsigned long long key =
                ((unsigned long long)float_ordered(dist) << 32) | (unsigned)gcol;
            ins2(key, m1, m2);
        }
        #pragma unroll
        for (int off = 8; off; off >>= 1) {
            unsigned long long o1 = __shfl_xor_sync(0xffffffffu, m1, off, 16);
            unsigned long long o2 = __shfl_xor_sync(0xffffffffu, m2, off, 16);
            ins2(o1, m1, m2);
            ins2(o2, m1, m2);
        }
        if (tx == 0) g_btop[blockIdx.y * M_TOTAL + grow] = make_ulonglong2(m1, m2);
    }
}

// ---------------------------------------------------------------------------
// Merge block top-2 -> global top-4, fp64 dots, then EMULATE the reference's
// fp32 rounding pipeline: d = fl32( fl32(qsq + esq_n) - 2*dot_n ).
// Lexicographic (d, index) min reproduces jnp.argmin incl. tie -> lowest idx.
__global__ void refine_kernel(const float* __restrict__ Q, const float* __restrict__ E) {
    int warp = threadIdx.x >> 5;
    int lane = threadIdx.x & 31;
    int q = blockIdx.x * 8 + warp;

    unsigned long long m[4] = {~0ULL, ~0ULL, ~0ULL, ~0ULL};
    #pragma unroll
    for (int b = lane; b < NBLK; b += 32) {
        ulonglong2 v = g_btop[b * M_TOTAL + q];
        ins4(v.x, m);
        ins4(v.y, m);
    }
    #pragma unroll
    for (int off = 16; off; off >>= 1) {
        #pragma unroll
        for (int t = 0; t < 4; t++) {
            unsigned long long o = __shfl_xor_sync(0xffffffffu, m[t], off);
            ins4(o, m);
        }
    }
    // all lanes now hold the same top-4
    int n0 = (int)(unsigned)(m[0] & 0xffffffffu);
    int n1 = (int)(unsigned)(m[1] & 0xffffffffu);
    int n2 = (int)(unsigned)(m[2] & 0xffffffffu);
    int n3 = (int)(unsigned)(m[3] & 0xffffffffu);

    const float* qr = Q + (size_t)q * KDIM;
    const float* e0 = E + (size_t)n0 * KDIM;
    const float* e1 = E + (size_t)n1 * KDIM;
    const float* e2 = E + (size_t)n2 * KDIM;
    const float* e3 = E + (size_t)n3 * KDIM;
    double d0 = 0.0, d1 = 0.0, d2 = 0.0, d3 = 0.0;
    #pragma unroll
    for (int c = lane; c < KDIM; c += 32) {
        double qv = (double)qr[c];
        d0 += qv * (double)e0[c];
        d1 += qv * (double)e1[c];
        d2 += qv * (double)e2[c];
        d3 += qv * (double)e3[c];
    }
    #pragma unroll
    for (int off = 16; off; off >>= 1) {
        d0 += __shfl_xor_sync(0xffffffffu, d0, off);
        d1 += __shfl_xor_sync(0xffffffffu, d1, off);
        d2 += __shfl_xor_sync(0xffffffffu, d2, off);
        d3 += __shfl_xor_sync(0xffffffffu, d3, off);
    }

    if (lane == 0) {
        float qsq = g_qsq[q];
        int   ns[4]   = {n0, n1, n2, n3};
        double ds[4]  = {d0, d1, d2, d3};
        unsigned long long best = ~0ULL;
        #pragma unroll
        for (int t = 0; t < 4; t++) {
            float A    = qsq + g_esq[ns[t]];         // fl32(qsq + esq) — ref step 1
            float dotf = (float)ds[t];               // ~ref's fp32 dot (±1e-6)
            float d    = fmaf(-2.0f, dotf, A);       // fl32(A - 2*dot) — ref step 2
            unsigned long long key =
                ((unsigned long long)float_ordered(d) << 32) | (unsigned)ns[t];
            best = (key < best) ? key : best;
        }
        g_final[q] = (int)(unsigned)(best & 0xffffffffu);
    }
}

// ---------------------------------------------------------------------------
__global__ void gather_kernel(const float* __restrict__ Q,
                              const float* __restrict__ E,
                              float* __restrict__ out) {
    int q = blockIdx.x;
    int idx = g_final[q];
    int c = threadIdx.x;

    float qv = Q[(size_t)q * KDIM + c];
    float ev = E[(size_t)idx * KDIM + c];
    out[(size_t)M_TOTAL + (size_t)q * KDIM + c] = qv + (ev - qv);

    float d = qv - ev;
    float s = d * d;
    #pragma unroll
    for (int off = 16; off; off >>= 1) s += __shfl_xor_sync(0xffffffffu, s, off);

    __shared__ float red[8];
    int lane = c & 31, warp = c >> 5;
    if (lane == 0) red[warp] = s;
    __syncthreads();
    if (c == 0) {
        float t = 0.f;
        #pragma unroll
        for (int w = 0; w < 8; w++) t += red[w];
        g_partial[q] = t;
        out[q] = (float)idx;
    }
}

// vq_loss = codebook + 0.25*commit = 1.25 * mean((q - quantized)^2)
__global__ void loss_kernel(float* __restrict__ out) {
    int tid = threadIdx.x;
    double s = 0.0;
    for (int i = tid; i < M_TOTAL; i += 256) s += (double)g_partial[i];
    #pragma unroll
    for (int off = 16; off; off >>= 1) s += __shfl_xor_sync(0xffffffffu, s, off);
    __shared__ double red[8];
    int lane = tid & 31, warp = tid >> 5;
    if (lane == 0) red[warp] = s;
    __syncthreads();
    if (tid == 0) {
        double t = 0.0;
        #pragma unroll
        for (int w = 0; w < 8; w++) t += red[w];
        double mean = t / (double)((size_t)M_TOTAL * KDIM);
        out[(size_t)M_TOTAL + (size_t)M_TOTAL * KDIM] = (float)(1.25 * mean);
    }
}

// ---------------------------------------------------------------------------
extern "C" void kernel_launch(void* const* d_in, const int* in_sizes, int n_in,
                              void* d_out, int out_size) {
    const float* Q = (const float*)d_in[0];
    const float* E = (const float*)d_in[1];
    float* out = (float*)d_out;

    esq_kernel<<<N_TOTAL / 8, 256>>>(E);
    qsq_kernel<<<M_TOTAL / 8, 256>>>(Q);

    dim3 grid(M_TOTAL / BM, N_TOTAL / BN);
    score_top2_kernel<<<grid, 256>>>(Q, E);

    refine_kernel<<<M_TOTAL / 8, 256>>>(Q, E);
    gather_kernel<<<M_TOTAL, KDIM>>>(Q, E, out);
    loss_kernel<<<1, 256>>>(out);
}